// round 14
// baseline (speedup 1.0000x reference)
#include <cuda_runtime.h>
#include <cuda_bf16.h>
#include <cuda_fp16.h>
#include <mma.h>
#include <math.h>
#include <cstdint>

using namespace nvcuda;

#define NHI 4096
#define NLO 262144
#define NT  (NHI + NLO)      /* 266240 = 260 * 1024 */
#define EHI 65536
#define ELO 524288
#define ET  (EHI + ELO)
#define DIM 128
#define KAUG 144             /* 128 + bias col + 15 zero pad */
#define NHEAD 4
#define HDIM 32
#define SCALE 0.17677669529663687f   /* 1/sqrt(32) */
#define NBLK 260             /* scan blocks */

// ---------------- scratch (device globals; no allocation allowed) ----------------
__device__ __half g_qh[(size_t)NT * DIM];    // q (fp16)
__device__ __half g_kvh[(size_t)NT * 256];   // k at +0, v at +128 (fp16)
__device__ __half g_hh[(size_t)NT * DIM];    // skip -> +agg+LN+relu in place (fp16)
__device__ int g_dcnt[NT];
__device__ int g_rowptr[NT + 1];
__device__ int g_cursor[NT];
__device__ int g_col[ET];
__device__ int g_bsum[NBLK];
__device__ int g_bex[NBLK];
// W^T fp16 image with bias row: [matrix 0..3][n 0..127][k 0..143]
__device__ __align__(16) __half g_wt[4 * 128 * KAUG];

// ---------------- helpers ----------------
__device__ __forceinline__ float warp_sum(float v) {
    #pragma unroll
    for (int o = 16; o; o >>= 1) v += __shfl_xor_sync(0xffffffffu, v, o);
    return v;
}
__device__ __forceinline__ uint32_t smem_u32(const void* p) {
    uint32_t a;
    asm("{ .reg .u64 t; cvta.to.shared.u64 t, %1; cvt.u32.u64 %0, t; }"
        : "=r"(a) : "l"(p));
    return a;
}
__device__ __forceinline__ void cp_async16(uint32_t dst, const void* src) {
    asm volatile("cp.async.cg.shared.global [%0], [%1], 16;" :: "r"(dst), "l"(src));
}
__device__ __forceinline__ float4 hf8_to_f4(uint2 raw) {
    __half2 h0 = ((const __half2*)&raw)[0];
    __half2 h1 = ((const __half2*)&raw)[1];
    float2 f0 = __half22float2(h0);
    float2 f1 = __half22float2(h1);
    return make_float4(f0.x, f0.y, f1.x, f1.y);
}
__device__ __forceinline__ uint2 f4_to_hf8(float4 x) {
    __half2 p0 = __floats2half2_rn(x.x, x.y);
    __half2 p1 = __floats2half2_rn(x.z, x.w);
    return make_uint2(*(uint32_t*)&p0, *(uint32_t*)&p1);
}

// ---------------- K0: prep weights -> W^T fp16 with bias row at k=128 ----------------
__global__ void prep_w(const float* __restrict__ Wq, const float* __restrict__ Wk,
                       const float* __restrict__ Wv, const float* __restrict__ Ws,
                       const float* __restrict__ bq, const float* __restrict__ bk,
                       const float* __restrict__ bv, const float* __restrict__ bs)
{
    int idx = blockIdx.x * 256 + threadIdx.x;  // 0..73727
    if (idx >= 4 * 128 * KAUG) return;
    int m = idx / (128 * KAUG);
    int rem = idx - m * 128 * KAUG;
    int n = rem / KAUG;
    int k = rem - n * KAUG;
    const float* W = (m == 0) ? Wq : (m == 1) ? Wk : (m == 2) ? Wv : Ws;
    const float* B = (m == 0) ? bq : (m == 1) ? bk : (m == 2) ? bv : bs;
    float w = (k < 128) ? W[k * 128 + n] : (k == 128 ? B[n] : 0.0f);
    g_wt[idx] = __float2half(w);
}

// ---------------- K1: fused QKV+skip GEMM, fp16 HMMA, K=144 (bias fused), no staging ----------------
// SMEM (half elems): A[64*144], B[128*144]
#define TILE_M 64
#define LDA KAUG                        /* 144 halfs = 288B row stride (conflict-free) */
#define A_ELEMS (TILE_M * LDA)          /* 9216 */
#define SM_B    A_ELEMS
#define SM_BYTES ((SM_B + 128 * LDA) * 2)   /* (9216+18432)*2 = 55296 */

__global__ void __launch_bounds__(128, 4)
gemm_hmma(const float* __restrict__ xh, const float* __restrict__ xl)
{
    extern __shared__ __half sm[];
    const uint32_t sbase = smem_u32(sm);
    const int t = threadIdx.x;       // 0..127
    const int wid = t >> 5;          // 0..3
    const int wm = wid & 1;          // warp row group: 32 rows
    const int wn = wid >> 1;         // warp col group: 64 cols

    // ---- load + convert A tile (64 rows x 128 k) to fp16; cols 128..143 = {1,0,...} ----
    const int row0 = blockIdx.x * TILE_M;
    const float* X = (row0 < NHI) ? (xh + (size_t)row0 * DIM)
                                  : (xl + (size_t)(row0 - NHI) * DIM);
    #pragma unroll
    for (int j = 0; j < 16; j++) {
        int v = t + 128 * j;            // float4 index 0..2047
        int r = v >> 5;                 // row 0..63
        int k0 = (v & 31) * 4;          // k 0..124
        float4 x = ((const float4*)X)[v];
        *(uint2*)(sm + r * LDA + k0) = f4_to_hf8(x);
    }
    {
        __half2 one0 = __floats2half2_rn(1.0f, 0.0f);
        uint32_t one_bits = *(uint32_t*)&one0;
        #pragma unroll
        for (int j = 0; j < 2; j++) {
            int u = t + 128 * j;        // 0..255
            int r = u >> 2;             // row 0..63
            int q = u & 3;              // which uint2 of the tail
            uint2 val = make_uint2(q == 0 ? one_bits : 0u, 0u);
            *(uint2*)(sm + r * LDA + 128 + q * 4) = val;
        }
    }

    #pragma unroll
    for (int m = 0; m < 4; m++) {
        if (m > 0) __syncthreads();     // all warps done with B[m-1] MMAs
        // load B[m]: 128 rows x 144 halfs = 2304 16B chunks
        {
            const uint4* gw = (const uint4*)(g_wt + (size_t)m * 128 * KAUG);
            uint32_t bb = sbase + SM_B * 2;
            #pragma unroll
            for (int j = 0; j < 18; j++) {
                int idx = t + 128 * j;      // 0..2303
                cp_async16(bb + (uint32_t)idx * 16, gw + idx);
            }
            asm volatile("cp.async.commit_group;");
            asm volatile("cp.async.wait_group 0;");
        }
        __syncthreads();   // B[m] (and A on m=0) visible to all

        const __half* B = sm + SM_B;

        wmma::fragment<wmma::accumulator, 16, 16, 16, float> acc[2][4];
        #pragma unroll
        for (int i = 0; i < 2; i++)
            #pragma unroll
            for (int j = 0; j < 4; j++)
                wmma::fill_fragment(acc[i][j], 0.0f);

        #pragma unroll
        for (int ks = 0; ks < 9; ks++) {
            wmma::fragment<wmma::matrix_a, 16, 16, 16, __half, wmma::row_major> af[2];
            #pragma unroll
            for (int i = 0; i < 2; i++)
                wmma::load_matrix_sync(af[i], sm + (wm * 32 + i * 16) * LDA + ks * 16, LDA);
            #pragma unroll
            for (int j = 0; j < 4; j++) {
                wmma::fragment<wmma::matrix_b, 16, 16, 16, __half, wmma::col_major> bf;
                wmma::load_matrix_sync(bf, B + (wn * 64 + j * 16) * LDA + ks * 16, LDA);
                wmma::mma_sync(acc[0][j], af[0], bf, acc[0][j]);
                wmma::mma_sync(acc[1][j], af[1], bf, acc[1][j]);
            }
        }

        // direct fp16 store to global (f32 acc -> f16 acc fragment, same element order)
        __half* dst;
        int ldo;
        if (m == 0)      { dst = g_qh  + (size_t)row0 * DIM; ldo = 128; }
        else if (m == 1) { dst = g_kvh + (size_t)row0 * 256; ldo = 256; }
        else if (m == 2) { dst = g_kvh + (size_t)row0 * 256 + 128; ldo = 256; }
        else             { dst = g_hh  + (size_t)row0 * DIM; ldo = 128; }

        #pragma unroll
        for (int i = 0; i < 2; i++)
            #pragma unroll
            for (int j = 0; j < 4; j++) {
                wmma::fragment<wmma::accumulator, 16, 16, 16, __half> hf;
                #pragma unroll
                for (int e = 0; e < hf.num_elements; e++)
                    hf.x[e] = __float2half(acc[i][j].x[e]);
                wmma::store_matrix_sync(
                    dst + (size_t)(wm * 32 + i * 16) * ldo + wn * 64 + j * 16,
                    hf, ldo, wmma::mem_row_major);
            }
    }
}

// ---------------- CSR build ----------------
__global__ void edge_hist(const int* __restrict__ eih, const int* __restrict__ eil)
{
    int e = blockIdx.x * 256 + threadIdx.x;
    if (e >= ET) return;
    int dst = (e < EHI) ? eih[EHI + e] : (eil[ELO + (e - EHI)] + NHI);
    atomicAdd(&g_dcnt[dst], 1);
}

__global__ void scan_local()
{
    __shared__ int sh[1024];
    const int t = threadIdx.x;
    const int i = blockIdx.x * 1024 + t;
    int v = g_dcnt[i];
    sh[t] = v;
    __syncthreads();
    #pragma unroll
    for (int off = 1; off < 1024; off <<= 1) {
        int u = (t >= off) ? sh[t - off] : 0;
        __syncthreads();
        sh[t] += u;
        __syncthreads();
    }
    g_rowptr[i] = sh[t] - v;            // local exclusive
    if (t == 1023) g_bsum[blockIdx.x] = sh[t];
}

__global__ void scan_bsum()
{
    __shared__ int sh[512];
    const int t = threadIdx.x;          // 512 threads
    int v = (t < NBLK) ? g_bsum[t] : 0;
    sh[t] = v;
    __syncthreads();
    #pragma unroll
    for (int off = 1; off < 512; off <<= 1) {
        int u = (t >= off) ? sh[t - off] : 0;
        __syncthreads();
        sh[t] += u;
        __syncthreads();
    }
    if (t < NBLK) g_bex[t] = sh[t] - v; // exclusive block base
    if (t == 511) g_rowptr[NT] = sh[511];
}

__global__ void scan_add()
{
    const int i = blockIdx.x * 1024 + threadIdx.x;
    int r = g_rowptr[i] + g_bex[blockIdx.x];
    g_rowptr[i] = r;
    g_cursor[i] = r;
}

__global__ void edge_scatter(const int* __restrict__ eih, const int* __restrict__ eil)
{
    int e = blockIdx.x * 256 + threadIdx.x;
    if (e >= ET) return;
    int src, dst;
    if (e < EHI) { src = eih[e];             dst = eih[EHI + e]; }
    else         { src = eil[e - EHI] + NHI; dst = eil[ELO + (e - EHI)] + NHI; }
    int pos = atomicAdd(&g_cursor[dst], 1);
    g_col[pos] = src;
}

// ---------------- K2: one-pass attention (online softmax) + fused LN/ReLU ----------------
// lane owns 4 contiguous columns [lane*4, lane*4+4); head = lane>>3.
__global__ void __launch_bounds__(256)
attn_ln(const float* __restrict__ lnw, const float* __restrict__ lnb)
{
    int node = blockIdx.x * 8 + threadIdx.y;
    int lane = threadIdx.x;
    int s = g_rowptr[node];
    int e1 = g_rowptr[node + 1];

    __half* hr = g_hh + (size_t)node * DIM;
    float4 val = hf8_to_f4(((uint2*)hr)[lane]);   // skip term

    if (s < e1) {
        float4 qv = hf8_to_f4(((const uint2*)(g_qh + (size_t)node * DIM))[lane]);

        float m = -INFINITY, d = 0.f;
        float4 acc = make_float4(0.f, 0.f, 0.f, 0.f);

        // 1-deep software pipeline on the kv gather (512B contiguous per edge)
        const uint2* kvp = (const uint2*)(g_kvh + (size_t)g_col[s] * 256);
        uint2 kraw = kvp[lane];
        uint2 vraw = kvp[lane + 32];
        for (int i = s; i < e1; i++) {
            float4 kc = hf8_to_f4(kraw);
            float4 vc = hf8_to_f4(vraw);
            if (i + 1 < e1) {
                const uint2* np = (const uint2*)(g_kvh + (size_t)g_col[i + 1] * 256);
                kraw = np[lane];
                vraw = np[lane + 32];
            }
            float p = qv.x * kc.x + qv.y * kc.y + qv.z * kc.z + qv.w * kc.w;
            p += __shfl_xor_sync(0xffffffffu, p, 4);
            p += __shfl_xor_sync(0xffffffffu, p, 2);
            p += __shfl_xor_sync(0xffffffffu, p, 1);
            float sc = p * SCALE;            // this lane's head score
            float mn = fmaxf(m, sc);
            float c = __expf(m - mn);        // 0 when m was -inf
            float w = __expf(sc - mn);
            d = d * c + w;
            acc.x = acc.x * c + w * vc.x;
            acc.y = acc.y * c + w * vc.y;
            acc.z = acc.z * c + w * vc.z;
            acc.w = acc.w * c + w * vc.w;
            m = mn;
        }
        float inv = 1.0f / d;
        val.x += acc.x * inv;
        val.y += acc.y * inv;
        val.z += acc.z * inv;
        val.w += acc.w * inv;
    }

    // fused LayerNorm + ReLU (warp holds the full 128-dim row)
    float sum = warp_sum(val.x + val.y + val.z + val.w);
    float sq = warp_sum(val.x * val.x + val.y * val.y + val.z * val.z + val.w * val.w);
    float mean = sum * (1.0f / 128.0f);
    float var = sq * (1.0f / 128.0f) - mean * mean;
    float rstd = rsqrtf(var + 1e-5f);
    float4 w4 = ((const float4*)lnw)[lane];
    float4 b4 = ((const float4*)lnb)[lane];
    float4 o;
    o.x = fmaxf((val.x - mean) * rstd * w4.x + b4.x, 0.0f);
    o.y = fmaxf((val.y - mean) * rstd * w4.y + b4.y, 0.0f);
    o.z = fmaxf((val.z - mean) * rstd * w4.z + b4.z, 0.0f);
    o.w = fmaxf((val.w - mean) * rstd * w4.w + b4.w, 0.0f);
    ((uint2*)hr)[lane] = f4_to_hf8(o);
}

// ---------------- K3: segmented pool + high-node gating (one warp per high node) ----------------
__device__ __forceinline__ int lower_bound_batch(const int* __restrict__ batch, int key)
{
    int lo = 0, hi = NLO;
    while (lo < hi) {
        int mid = (lo + hi) >> 1;
        if (batch[mid] < key) lo = mid + 1; else hi = mid;
    }
    return lo;
}

__global__ void __launch_bounds__(256)
pool_final_high(const int* __restrict__ batch, const float* __restrict__ wlh,
                float* __restrict__ out)
{
    int g = blockIdx.x * 8 + threadIdx.y;
    int lane = threadIdx.x;
    int lb = lower_bound_batch(batch, g);
    int ub = lower_bound_batch(batch, g + 1);

    float4 s = make_float4(0.f, 0.f, 0.f, 0.f);
    for (int j = lb; j < ub; j++) {
        float4 lr = hf8_to_f4(((const uint2*)(g_hh + (size_t)(NHI + j) * DIM))[lane]);
        s.x += lr.x; s.y += lr.y; s.z += lr.z; s.w += lr.w;
    }
    float inv = 1.0f / fmaxf((float)(ub - lb), 1.0f);
    float4 pv = make_float4(s.x * inv, s.y * inv, s.z * inv, s.w * inv);

    float4 hv = hf8_to_f4(((const uint2*)(g_hh + (size_t)g * DIM))[lane]);
    float4 w0 = ((const float4*)wlh)[lane];
    float4 w1 = ((const float4*)(wlh + DIM))[lane];
    float dot = hv.x * w0.x + hv.y * w0.y + hv.z * w0.z + hv.w * w0.w
              + pv.x * w1.x + pv.y * w1.y + pv.z * w1.z + pv.w * w1.w;
    dot = warp_sum(dot);
    float sgm = 1.0f / (1.0f + __expf(-dot));
    float4 o;
    o.x = sgm * hv.x + (1.0f - sgm) * pv.x;
    o.y = sgm * hv.y + (1.0f - sgm) * pv.y;
    o.z = sgm * hv.z + (1.0f - sgm) * pv.z;
    o.w = sgm * hv.w + (1.0f - sgm) * pv.w;
    ((float4*)(out + (size_t)g * DIM))[lane] = o;
}

// ---------------- K4: low-node gating epilogue ----------------
__global__ void final_low(const float* __restrict__ whl, const int* __restrict__ batch,
                          float* __restrict__ out)
{
    int j = blockIdx.x * 8 + threadIdx.y;
    int lane = threadIdx.x;
    int g = batch[j];
    float4 hb = hf8_to_f4(((const uint2*)(g_hh + (size_t)g * DIM))[lane]);
    float4 lv = hf8_to_f4(((const uint2*)(g_hh + (size_t)(NHI + j) * DIM))[lane]);
    float4 w0 = ((const float4*)whl)[lane];
    float4 w1 = ((const float4*)(whl + DIM))[lane];
    float d = hb.x * w0.x + hb.y * w0.y + hb.z * w0.z + hb.w * w0.w
            + lv.x * w1.x + lv.y * w1.y + lv.z * w1.z + lv.w * w1.w;
    d = warp_sum(d);
    float a = 1.0f / (1.0f + __expf(-d));
    float4 o;
    o.x = a * lv.x + (1.0f - a) * hb.x;
    o.y = a * lv.y + (1.0f - a) * hb.y;
    o.z = a * lv.z + (1.0f - a) * hb.z;
    o.w = a * lv.w + (1.0f - a) * hb.w;
    ((float4*)(out + (size_t)j * DIM))[lane] = o;
}

// ---------------- launch ----------------
extern "C" void kernel_launch(void* const* d_in, const int* in_sizes, int n_in,
                              void* d_out, int out_size)
{
    const float* high_emb = (const float*)d_in[0];
    const float* low_emb  = (const float*)d_in[1];
    const float* Wq = (const float*)d_in[2];  const float* bq = (const float*)d_in[3];
    const float* Wk = (const float*)d_in[4];  const float* bk = (const float*)d_in[5];
    const float* Wv = (const float*)d_in[6];  const float* bv = (const float*)d_in[7];
    const float* Ws = (const float*)d_in[8];  const float* bs = (const float*)d_in[9];
    const float* lnw = (const float*)d_in[10];
    const float* lnb = (const float*)d_in[11];
    const float* wlh = (const float*)d_in[12];
    const float* whl = (const float*)d_in[13];
    const int* eih   = (const int*)d_in[14];
    const int* eil   = (const int*)d_in[15];
    const int* batch = (const int*)d_in[16];
    float* out = (float*)d_out;

    void* pcnt;
    cudaGetSymbolAddress(&pcnt, g_dcnt);

    cudaFuncSetAttribute(gemm_hmma, cudaFuncAttributeMaxDynamicSharedMemorySize, SM_BYTES);

    // second stream + fork/join events (graph-capture-legal pattern)
    cudaStream_t s2;
    cudaStreamCreateWithFlags(&s2, cudaStreamNonBlocking);
    cudaEvent_t evFork, evCsr, evAttn, evPool;
    cudaEventCreateWithFlags(&evFork, cudaEventDisableTiming);
    cudaEventCreateWithFlags(&evCsr,  cudaEventDisableTiming);
    cudaEventCreateWithFlags(&evAttn, cudaEventDisableTiming);
    cudaEventCreateWithFlags(&evPool, cudaEventDisableTiming);

    cudaMemsetAsync(pcnt, 0, NT * sizeof(int), 0);
    cudaEventRecord(evFork, 0);
    cudaStreamWaitEvent(s2, evFork, 0);

    // stream 0: prep + GEMM (profiled slot); s2: CSR chain concurrently
    prep_w<<<288, 256>>>(Wq, Wk, Wv, Ws, bq, bk, bv, bs);
    edge_hist<<<(ET + 255) / 256, 256, 0, s2>>>(eih, eil);
    gemm_hmma<<<NT / TILE_M, 128, SM_BYTES>>>(high_emb, low_emb);

    scan_local<<<NBLK, 1024, 0, s2>>>();
    scan_bsum<<<1, 512, 0, s2>>>();
    scan_add<<<NBLK, 1024, 0, s2>>>();
    edge_scatter<<<(ET + 255) / 256, 256, 0, s2>>>(eih, eil);
    cudaEventRecord(evCsr, s2);

    // join: attention needs both GEMM outputs and CSR
    cudaStreamWaitEvent(0, evCsr, 0);
    dim3 t32x8(32, 8);
    attn_ln<<<NT / 8, t32x8>>>(lnw, lnb);
    cudaEventRecord(evAttn, 0);

    // overlap the two epilogues
    cudaStreamWaitEvent(s2, evAttn, 0);
    pool_final_high<<<NHI / 8, t32x8, 0, s2>>>(batch, wlh, out);
    cudaEventRecord(evPool, s2);
    final_low<<<NLO / 8, t32x8>>>(whl, batch, out + (size_t)NHI * DIM);
    cudaStreamWaitEvent(0, evPool, 0);

    cudaEventDestroy(evFork);
    cudaEventDestroy(evCsr);
    cudaEventDestroy(evAttn);
    cudaEventDestroy(evPool);
    cudaStreamDestroy(s2);
}

// round 15
// speedup vs baseline: 1.0049x; 1.0049x over previous
#include <cuda_runtime.h>
#include <cuda_bf16.h>
#include <cuda_fp16.h>
#include <mma.h>
#include <math.h>
#include <cstdint>

using namespace nvcuda;

#define NHI 4096
#define NLO 262144
#define NT  (NHI + NLO)      /* 266240 = 260 * 1024 */
#define EHI 65536
#define ELO 524288
#define ET  (EHI + ELO)
#define DIM 128
#define KAUG 144             /* 128 + bias col + 15 zero pad */
#define NHEAD 4
#define HDIM 32
#define SCALE 0.17677669529663687f   /* 1/sqrt(32) */
#define NBLK 260             /* scan blocks */

// ---------------- scratch (device globals; no allocation allowed) ----------------
__device__ __half g_qh[(size_t)NT * DIM];    // q (fp16)
__device__ __half g_kvh[(size_t)NT * 256];   // k at +0, v at +128 (fp16)
__device__ __half g_hh[(size_t)NT * DIM];    // skip -> +agg+LN+relu in place (fp16)
__device__ int g_dcnt[NT];
__device__ int g_rowptr[NT + 1];
__device__ int g_cursor[NT];
__device__ int g_col[ET];
__device__ int g_bsum[NBLK];
__device__ int g_bex[NBLK];
// W^T fp16 image with bias row: [matrix 0..3][n 0..127][k 0..143]
__device__ __align__(16) __half g_wt[4 * 128 * KAUG];

// ---------------- helpers ----------------
__device__ __forceinline__ float warp_sum(float v) {
    #pragma unroll
    for (int o = 16; o; o >>= 1) v += __shfl_xor_sync(0xffffffffu, v, o);
    return v;
}
__device__ __forceinline__ uint32_t smem_u32(const void* p) {
    uint32_t a;
    asm("{ .reg .u64 t; cvta.to.shared.u64 t, %1; cvt.u32.u64 %0, t; }"
        : "=r"(a) : "l"(p));
    return a;
}
__device__ __forceinline__ void cp_async16(uint32_t dst, const void* src) {
    asm volatile("cp.async.cg.shared.global [%0], [%1], 16;" :: "r"(dst), "l"(src));
}
__device__ __forceinline__ float4 hf8_to_f4(uint2 raw) {
    __half2 h0 = ((const __half2*)&raw)[0];
    __half2 h1 = ((const __half2*)&raw)[1];
    float2 f0 = __half22float2(h0);
    float2 f1 = __half22float2(h1);
    return make_float4(f0.x, f0.y, f1.x, f1.y);
}
__device__ __forceinline__ uint2 f4_to_hf8(float4 x) {
    __half2 p0 = __floats2half2_rn(x.x, x.y);
    __half2 p1 = __floats2half2_rn(x.z, x.w);
    return make_uint2(*(uint32_t*)&p0, *(uint32_t*)&p1);
}

// ---------------- K0: prep weights -> W^T fp16 with bias row at k=128 ----------------
__global__ void prep_w(const float* __restrict__ Wq, const float* __restrict__ Wk,
                       const float* __restrict__ Wv, const float* __restrict__ Ws,
                       const float* __restrict__ bq, const float* __restrict__ bk,
                       const float* __restrict__ bv, const float* __restrict__ bs)
{
    int idx = blockIdx.x * 256 + threadIdx.x;  // 0..73727
    if (idx >= 4 * 128 * KAUG) return;
    int m = idx / (128 * KAUG);
    int rem = idx - m * 128 * KAUG;
    int n = rem / KAUG;
    int k = rem - n * KAUG;
    const float* W = (m == 0) ? Wq : (m == 1) ? Wk : (m == 2) ? Wv : Ws;
    const float* B = (m == 0) ? bq : (m == 1) ? bk : (m == 2) ? bv : bs;
    float w = (k < 128) ? W[k * 128 + n] : (k == 128 ? B[n] : 0.0f);
    g_wt[idx] = __float2half(w);
}

// ---------------- K1: fused QKV+skip GEMM, fp16 HMMA, K=144 (bias fused), no staging ----------------
// SMEM (half elems): A[64*144], B[128*144]
#define TILE_M 64
#define LDA KAUG                        /* 144 halfs = 288B row stride (conflict-free) */
#define A_ELEMS (TILE_M * LDA)          /* 9216 */
#define SM_B    A_ELEMS
#define SM_BYTES ((SM_B + 128 * LDA) * 2)   /* (9216+18432)*2 = 55296 */

__global__ void __launch_bounds__(128, 4)
gemm_hmma(const float* __restrict__ xh, const float* __restrict__ xl)
{
    extern __shared__ __half sm[];
    const uint32_t sbase = smem_u32(sm);
    const int t = threadIdx.x;       // 0..127
    const int wid = t >> 5;          // 0..3
    const int wm = wid & 1;          // warp row group: 32 rows
    const int wn = wid >> 1;         // warp col group: 64 cols

    // ---- load + convert A tile (64 rows x 128 k) to fp16; cols 128..143 = {1,0,...} ----
    const int row0 = blockIdx.x * TILE_M;
    const float* X = (row0 < NHI) ? (xh + (size_t)row0 * DIM)
                                  : (xl + (size_t)(row0 - NHI) * DIM);
    #pragma unroll
    for (int j = 0; j < 16; j++) {
        int v = t + 128 * j;            // float4 index 0..2047
        int r = v >> 5;                 // row 0..63
        int k0 = (v & 31) * 4;          // k 0..124
        float4 x = ((const float4*)X)[v];
        *(uint2*)(sm + r * LDA + k0) = f4_to_hf8(x);
    }
    {
        __half2 one0 = __floats2half2_rn(1.0f, 0.0f);
        uint32_t one_bits = *(uint32_t*)&one0;
        #pragma unroll
        for (int j = 0; j < 2; j++) {
            int u = t + 128 * j;        // 0..255
            int r = u >> 2;             // row 0..63
            int q = u & 3;              // which uint2 of the tail
            uint2 val = make_uint2(q == 0 ? one_bits : 0u, 0u);
            *(uint2*)(sm + r * LDA + 128 + q * 4) = val;
        }
    }

    #pragma unroll
    for (int m = 0; m < 4; m++) {
        if (m > 0) __syncthreads();     // all warps done with B[m-1] MMAs
        // load B[m]: 128 rows x 144 halfs = 2304 16B chunks
        {
            const uint4* gw = (const uint4*)(g_wt + (size_t)m * 128 * KAUG);
            uint32_t bb = sbase + SM_B * 2;
            #pragma unroll
            for (int j = 0; j < 18; j++) {
                int idx = t + 128 * j;      // 0..2303
                cp_async16(bb + (uint32_t)idx * 16, gw + idx);
            }
            asm volatile("cp.async.commit_group;");
            asm volatile("cp.async.wait_group 0;");
        }
        __syncthreads();   // B[m] (and A on m=0) visible to all

        const __half* B = sm + SM_B;

        wmma::fragment<wmma::accumulator, 16, 16, 16, float> acc[2][4];
        #pragma unroll
        for (int i = 0; i < 2; i++)
            #pragma unroll
            for (int j = 0; j < 4; j++)
                wmma::fill_fragment(acc[i][j], 0.0f);

        #pragma unroll
        for (int ks = 0; ks < 9; ks++) {
            wmma::fragment<wmma::matrix_a, 16, 16, 16, __half, wmma::row_major> af[2];
            #pragma unroll
            for (int i = 0; i < 2; i++)
                wmma::load_matrix_sync(af[i], sm + (wm * 32 + i * 16) * LDA + ks * 16, LDA);
            #pragma unroll
            for (int j = 0; j < 4; j++) {
                wmma::fragment<wmma::matrix_b, 16, 16, 16, __half, wmma::col_major> bf;
                wmma::load_matrix_sync(bf, B + (wn * 64 + j * 16) * LDA + ks * 16, LDA);
                wmma::mma_sync(acc[0][j], af[0], bf, acc[0][j]);
                wmma::mma_sync(acc[1][j], af[1], bf, acc[1][j]);
            }
        }

        // direct fp16 store to global (f32 acc -> f16 acc fragment, same element order)
        __half* dst;
        int ldo;
        if (m == 0)      { dst = g_qh  + (size_t)row0 * DIM; ldo = 128; }
        else if (m == 1) { dst = g_kvh + (size_t)row0 * 256; ldo = 256; }
        else if (m == 2) { dst = g_kvh + (size_t)row0 * 256 + 128; ldo = 256; }
        else             { dst = g_hh  + (size_t)row0 * DIM; ldo = 128; }

        #pragma unroll
        for (int i = 0; i < 2; i++)
            #pragma unroll
            for (int j = 0; j < 4; j++) {
                wmma::fragment<wmma::accumulator, 16, 16, 16, __half> hf;
                #pragma unroll
                for (int e = 0; e < hf.num_elements; e++)
                    hf.x[e] = __float2half(acc[i][j].x[e]);
                wmma::store_matrix_sync(
                    dst + (size_t)(wm * 32 + i * 16) * ldo + wn * 64 + j * 16,
                    hf, ldo, wmma::mem_row_major);
            }
    }
}

// ---------------- CSR build ----------------
__global__ void edge_hist(const int* __restrict__ eih, const int* __restrict__ eil)
{
    int e = blockIdx.x * 256 + threadIdx.x;
    if (e >= ET) return;
    int dst = (e < EHI) ? eih[EHI + e] : (eil[ELO + (e - EHI)] + NHI);
    atomicAdd(&g_dcnt[dst], 1);
}

__global__ void scan_local()
{
    __shared__ int sh[1024];
    const int t = threadIdx.x;
    const int i = blockIdx.x * 1024 + t;
    int v = g_dcnt[i];
    sh[t] = v;
    __syncthreads();
    #pragma unroll
    for (int off = 1; off < 1024; off <<= 1) {
        int u = (t >= off) ? sh[t - off] : 0;
        __syncthreads();
        sh[t] += u;
        __syncthreads();
    }
    g_rowptr[i] = sh[t] - v;            // local exclusive
    if (t == 1023) g_bsum[blockIdx.x] = sh[t];
}

__global__ void scan_bsum()
{
    __shared__ int sh[512];
    const int t = threadIdx.x;          // 512 threads
    int v = (t < NBLK) ? g_bsum[t] : 0;
    sh[t] = v;
    __syncthreads();
    #pragma unroll
    for (int off = 1; off < 512; off <<= 1) {
        int u = (t >= off) ? sh[t - off] : 0;
        __syncthreads();
        sh[t] += u;
        __syncthreads();
    }
    if (t < NBLK) g_bex[t] = sh[t] - v; // exclusive block base
    if (t == 511) g_rowptr[NT] = sh[511];
}

__global__ void scan_add()
{
    const int i = blockIdx.x * 1024 + threadIdx.x;
    int r = g_rowptr[i] + g_bex[blockIdx.x];
    g_rowptr[i] = r;
    g_cursor[i] = r;
}

__global__ void edge_scatter(const int* __restrict__ eih, const int* __restrict__ eil)
{
    int e = blockIdx.x * 256 + threadIdx.x;
    if (e >= ET) return;
    int src, dst;
    if (e < EHI) { src = eih[e];             dst = eih[EHI + e]; }
    else         { src = eil[e - EHI] + NHI; dst = eil[ELO + (e - EHI)] + NHI; }
    int pos = atomicAdd(&g_cursor[dst], 1);
    g_col[pos] = src;
}

// ---------------- K2: one-pass attention (plain exp; softmax is shift-invariant and
// scores are bounded ~|q||k|*SCALE < 25, far inside fp32 exp range) + fused LN/ReLU ----
// lane owns 4 contiguous columns [lane*4, lane*4+4); head = lane>>3.
__global__ void __launch_bounds__(256)
attn_ln(const float* __restrict__ lnw, const float* __restrict__ lnb)
{
    int node = blockIdx.x * 8 + threadIdx.y;
    int lane = threadIdx.x;
    int s = g_rowptr[node];
    int e1 = g_rowptr[node + 1];

    __half* hr = g_hh + (size_t)node * DIM;
    float4 val = hf8_to_f4(((uint2*)hr)[lane]);   // skip term

    if (s < e1) {
        float4 qv = hf8_to_f4(((const uint2*)(g_qh + (size_t)node * DIM))[lane]);

        float d = 0.f;
        float4 acc = make_float4(0.f, 0.f, 0.f, 0.f);

        // 1-deep software pipeline on the kv gather (512B contiguous per edge)
        const uint2* kvp = (const uint2*)(g_kvh + (size_t)g_col[s] * 256);
        uint2 kraw = kvp[lane];
        uint2 vraw = kvp[lane + 32];
        for (int i = s; i < e1; i++) {
            float4 kc = hf8_to_f4(kraw);
            float4 vc = hf8_to_f4(vraw);
            if (i + 1 < e1) {
                const uint2* np = (const uint2*)(g_kvh + (size_t)g_col[i + 1] * 256);
                kraw = np[lane];
                vraw = np[lane + 32];
            }
            float p = qv.x * kc.x + qv.y * kc.y + qv.z * kc.z + qv.w * kc.w;
            p += __shfl_xor_sync(0xffffffffu, p, 4);
            p += __shfl_xor_sync(0xffffffffu, p, 2);
            p += __shfl_xor_sync(0xffffffffu, p, 1);
            float w = __expf(p * SCALE);     // this lane's head weight
            d += w;
            acc.x += w * vc.x;
            acc.y += w * vc.y;
            acc.z += w * vc.z;
            acc.w += w * vc.w;
        }
        float inv = 1.0f / d;
        val.x += acc.x * inv;
        val.y += acc.y * inv;
        val.z += acc.z * inv;
        val.w += acc.w * inv;
    }

    // fused LayerNorm + ReLU (warp holds the full 128-dim row)
    float sum = warp_sum(val.x + val.y + val.z + val.w);
    float sq = warp_sum(val.x * val.x + val.y * val.y + val.z * val.z + val.w * val.w);
    float mean = sum * (1.0f / 128.0f);
    float var = sq * (1.0f / 128.0f) - mean * mean;
    float rstd = rsqrtf(var + 1e-5f);
    float4 w4 = ((const float4*)lnw)[lane];
    float4 b4 = ((const float4*)lnb)[lane];
    float4 o;
    o.x = fmaxf((val.x - mean) * rstd * w4.x + b4.x, 0.0f);
    o.y = fmaxf((val.y - mean) * rstd * w4.y + b4.y, 0.0f);
    o.z = fmaxf((val.z - mean) * rstd * w4.z + b4.z, 0.0f);
    o.w = fmaxf((val.w - mean) * rstd * w4.w + b4.w, 0.0f);
    ((uint2*)hr)[lane] = f4_to_hf8(o);
}

// ---------------- K3: segmented pool + high-node gating (one warp per high node) ----------------
__device__ __forceinline__ int lower_bound_batch(const int* __restrict__ batch, int key)
{
    int lo = 0, hi = NLO;
    while (lo < hi) {
        int mid = (lo + hi) >> 1;
        if (batch[mid] < key) lo = mid + 1; else hi = mid;
    }
    return lo;
}

__global__ void __launch_bounds__(256)
pool_final_high(const int* __restrict__ batch, const float* __restrict__ wlh,
                float* __restrict__ out)
{
    int g = blockIdx.x * 8 + threadIdx.y;
    int lane = threadIdx.x;
    int lb = lower_bound_batch(batch, g);
    int ub = lower_bound_batch(batch, g + 1);

    float4 s = make_float4(0.f, 0.f, 0.f, 0.f);
    for (int j = lb; j < ub; j++) {
        float4 lr = hf8_to_f4(((const uint2*)(g_hh + (size_t)(NHI + j) * DIM))[lane]);
        s.x += lr.x; s.y += lr.y; s.z += lr.z; s.w += lr.w;
    }
    float inv = 1.0f / fmaxf((float)(ub - lb), 1.0f);
    float4 pv = make_float4(s.x * inv, s.y * inv, s.z * inv, s.w * inv);

    float4 hv = hf8_to_f4(((const uint2*)(g_hh + (size_t)g * DIM))[lane]);
    float4 w0 = ((const float4*)wlh)[lane];
    float4 w1 = ((const float4*)(wlh + DIM))[lane];
    float dot = hv.x * w0.x + hv.y * w0.y + hv.z * w0.z + hv.w * w0.w
              + pv.x * w1.x + pv.y * w1.y + pv.z * w1.z + pv.w * w1.w;
    dot = warp_sum(dot);
    float sgm = 1.0f / (1.0f + __expf(-dot));
    float4 o;
    o.x = sgm * hv.x + (1.0f - sgm) * pv.x;
    o.y = sgm * hv.y + (1.0f - sgm) * pv.y;
    o.z = sgm * hv.z + (1.0f - sgm) * pv.z;
    o.w = sgm * hv.w + (1.0f - sgm) * pv.w;
    ((float4*)(out + (size_t)g * DIM))[lane] = o;
}

// ---------------- K4: low-node gating epilogue ----------------
__global__ void final_low(const float* __restrict__ whl, const int* __restrict__ batch,
                          float* __restrict__ out)
{
    int j = blockIdx.x * 8 + threadIdx.y;
    int lane = threadIdx.x;
    int g = batch[j];
    float4 hb = hf8_to_f4(((const uint2*)(g_hh + (size_t)g * DIM))[lane]);
    float4 lv = hf8_to_f4(((const uint2*)(g_hh + (size_t)(NHI + j) * DIM))[lane]);
    float4 w0 = ((const float4*)whl)[lane];
    float4 w1 = ((const float4*)(whl + DIM))[lane];
    float d = hb.x * w0.x + hb.y * w0.y + hb.z * w0.z + hb.w * w0.w
            + lv.x * w1.x + lv.y * w1.y + lv.z * w1.z + lv.w * w1.w;
    d = warp_sum(d);
    float a = 1.0f / (1.0f + __expf(-d));
    float4 o;
    o.x = a * lv.x + (1.0f - a) * hb.x;
    o.y = a * lv.y + (1.0f - a) * hb.y;
    o.z = a * lv.z + (1.0f - a) * hb.z;
    o.w = a * lv.w + (1.0f - a) * hb.w;
    ((float4*)(out + (size_t)j * DIM))[lane] = o;
}

// ---------------- launch ----------------
extern "C" void kernel_launch(void* const* d_in, const int* in_sizes, int n_in,
                              void* d_out, int out_size)
{
    const float* high_emb = (const float*)d_in[0];
    const float* low_emb  = (const float*)d_in[1];
    const float* Wq = (const float*)d_in[2];  const float* bq = (const float*)d_in[3];
    const float* Wk = (const float*)d_in[4];  const float* bk = (const float*)d_in[5];
    const float* Wv = (const float*)d_in[6];  const float* bv = (const float*)d_in[7];
    const float* Ws = (const float*)d_in[8];  const float* bs = (const float*)d_in[9];
    const float* lnw = (const float*)d_in[10];
    const float* lnb = (const float*)d_in[11];
    const float* wlh = (const float*)d_in[12];
    const float* whl = (const float*)d_in[13];
    const int* eih   = (const int*)d_in[14];
    const int* eil   = (const int*)d_in[15];
    const int* batch = (const int*)d_in[16];
    float* out = (float*)d_out;

    void* pcnt;
    cudaGetSymbolAddress(&pcnt, g_dcnt);

    cudaFuncSetAttribute(gemm_hmma, cudaFuncAttributeMaxDynamicSharedMemorySize, SM_BYTES);

    // second stream + fork/join events (graph-capture-legal pattern)
    cudaStream_t s2;
    cudaStreamCreateWithFlags(&s2, cudaStreamNonBlocking);
    cudaEvent_t evFork, evCsr, evAttn, evPool;
    cudaEventCreateWithFlags(&evFork, cudaEventDisableTiming);
    cudaEventCreateWithFlags(&evCsr,  cudaEventDisableTiming);
    cudaEventCreateWithFlags(&evAttn, cudaEventDisableTiming);
    cudaEventCreateWithFlags(&evPool, cudaEventDisableTiming);

    cudaMemsetAsync(pcnt, 0, NT * sizeof(int), 0);
    cudaEventRecord(evFork, 0);
    cudaStreamWaitEvent(s2, evFork, 0);

    // stream 0: prep + GEMM; s2: CSR chain concurrently
    prep_w<<<288, 256>>>(Wq, Wk, Wv, Ws, bq, bk, bv, bs);
    edge_hist<<<(ET + 255) / 256, 256, 0, s2>>>(eih, eil);
    gemm_hmma<<<NT / TILE_M, 128, SM_BYTES>>>(high_emb, low_emb);

    scan_local<<<NBLK, 1024, 0, s2>>>();
    scan_bsum<<<1, 512, 0, s2>>>();
    scan_add<<<NBLK, 1024, 0, s2>>>();
    edge_scatter<<<(ET + 255) / 256, 256, 0, s2>>>(eih, eil);
    cudaEventRecord(evCsr, s2);

    // join: attention needs both GEMM outputs and CSR
    cudaStreamWaitEvent(0, evCsr, 0);
    dim3 t32x8(32, 8);
    attn_ln<<<NT / 8, t32x8>>>(lnw, lnb);
    cudaEventRecord(evAttn, 0);

    // overlap the two epilogues
    cudaStreamWaitEvent(s2, evAttn, 0);
    pool_final_high<<<NHI / 8, t32x8, 0, s2>>>(batch, wlh, out);
    cudaEventRecord(evPool, s2);
    final_low<<<NLO / 8, t32x8>>>(whl, batch, out + (size_t)NHI * DIM);
    cudaStreamWaitEvent(0, evPool, 0);

    cudaEventDestroy(evFork);
    cudaEventDestroy(evCsr);
    cudaEventDestroy(evAttn);
    cudaEventDestroy(evPool);
    cudaStreamDestroy(s2);
}

// round 16
// speedup vs baseline: 1.0955x; 1.0901x over previous
#include <cuda_runtime.h>
#include <cuda_bf16.h>
#include <cuda_fp16.h>
#include <mma.h>
#include <math.h>
#include <cstdint>

using namespace nvcuda;

#define NHI 4096
#define NLO 262144
#define NT  (NHI + NLO)      /* 266240 = 260 * 1024 */
#define EHI 65536
#define ELO 524288
#define ET  (EHI + ELO)
#define DIM 128
#define KAUG 144             /* 128 + bias col + 15 zero pad (K extent for MMA) */
#define NHEAD 4
#define HDIM 32
#define SCALE 0.17677669529663687f   /* 1/sqrt(32) */
#define NBLK 260             /* scan blocks */

// ---------------- scratch (device globals; no allocation allowed) ----------------
__device__ __half g_qh[(size_t)NT * DIM];    // q (fp16)
__device__ __half g_kvh[(size_t)NT * 256];   // k at +0, v at +128 (fp16)
__device__ __half g_hh[(size_t)NT * DIM];    // skip -> +agg+LN+relu in place (fp16)
__device__ int g_dcnt[NT];
__device__ int g_rowptr[NT + 1];
__device__ int g_cursor[NT];
__device__ int g_col[ET];
__device__ int g_bsum[NBLK];
__device__ int g_bex[NBLK];
// W^T fp16 image with bias row: [matrix 0..3][n 0..127][k 0..143]
__device__ __align__(16) __half g_wt[4 * 128 * KAUG];

// ---------------- helpers ----------------
__device__ __forceinline__ float warp_sum(float v) {
    #pragma unroll
    for (int o = 16; o; o >>= 1) v += __shfl_xor_sync(0xffffffffu, v, o);
    return v;
}
__device__ __forceinline__ uint32_t smem_u32(const void* p) {
    uint32_t a;
    asm("{ .reg .u64 t; cvta.to.shared.u64 t, %1; cvt.u32.u64 %0, t; }"
        : "=r"(a) : "l"(p));
    return a;
}
__device__ __forceinline__ void cp_async16(uint32_t dst, const void* src) {
    asm volatile("cp.async.cg.shared.global [%0], [%1], 16;" :: "r"(dst), "l"(src));
}
__device__ __forceinline__ float4 hf8_to_f4(uint2 raw) {
    __half2 h0 = ((const __half2*)&raw)[0];
    __half2 h1 = ((const __half2*)&raw)[1];
    float2 f0 = __half22float2(h0);
    float2 f1 = __half22float2(h1);
    return make_float4(f0.x, f0.y, f1.x, f1.y);
}
__device__ __forceinline__ uint2 f4_to_hf8(float4 x) {
    __half2 p0 = __floats2half2_rn(x.x, x.y);
    __half2 p1 = __floats2half2_rn(x.z, x.w);
    return make_uint2(*(uint32_t*)&p0, *(uint32_t*)&p1);
}

// ---------------- K0: prep weights -> W^T fp16 with bias row at k=128 ----------------
__global__ void prep_w(const float* __restrict__ Wq, const float* __restrict__ Wk,
                       const float* __restrict__ Wv, const float* __restrict__ Ws,
                       const float* __restrict__ bq, const float* __restrict__ bk,
                       const float* __restrict__ bv, const float* __restrict__ bs)
{
    int idx = blockIdx.x * 256 + threadIdx.x;  // 0..73727
    if (idx >= 4 * 128 * KAUG) return;
    int m = idx / (128 * KAUG);
    int rem = idx - m * 128 * KAUG;
    int n = rem / KAUG;
    int k = rem - n * KAUG;
    const float* W = (m == 0) ? Wq : (m == 1) ? Wk : (m == 2) ? Wv : Ws;
    const float* B = (m == 0) ? bq : (m == 1) ? bk : (m == 2) ? bv : bs;
    float w = (k < 128) ? W[k * 128 + n] : (k == 128 ? B[n] : 0.0f);
    g_wt[idx] = __float2half(w);
}

// ---------------- K1: fused QKV+skip GEMM, fp16 HMMA, K=144, LDA=152 (conflict-free) ----------------
// LDA = 152 halfs = 304B = 19 x 16B units (odd) -> ldmatrix conflict-free.
// SMEM (half elems): A[64*152], B[128*152]
#define TILE_M 64
#define LDA 152
#define A_ELEMS (TILE_M * LDA)          /* 9728 */
#define SM_B    A_ELEMS
#define SM_BYTES ((SM_B + 128 * LDA) * 2)   /* (9728+19456)*2 = 58368 */

__global__ void __launch_bounds__(128, 3)
gemm_hmma(const float* __restrict__ xh, const float* __restrict__ xl)
{
    extern __shared__ __half sm[];
    const uint32_t sbase = smem_u32(sm);
    const int t = threadIdx.x;       // 0..127
    const int wid = t >> 5;          // 0..3
    const int wm = wid & 1;          // warp row group: 32 rows
    const int wn = wid >> 1;         // warp col group: 64 cols

    // ---- load + convert A tile (64 rows x 128 k) to fp16; cols 128..143 = {1,0,...} ----
    const int row0 = blockIdx.x * TILE_M;
    const float* X = (row0 < NHI) ? (xh + (size_t)row0 * DIM)
                                  : (xl + (size_t)(row0 - NHI) * DIM);
    #pragma unroll
    for (int j = 0; j < 16; j++) {
        int v = t + 128 * j;            // float4 index 0..2047
        int r = v >> 5;                 // row 0..63
        int k0 = (v & 31) * 4;          // k 0..124
        float4 x = ((const float4*)X)[v];
        *(uint2*)(sm + r * LDA + k0) = f4_to_hf8(x);
    }
    {
        __half2 one0 = __floats2half2_rn(1.0f, 0.0f);
        uint32_t one_bits = *(uint32_t*)&one0;
        #pragma unroll
        for (int j = 0; j < 2; j++) {
            int u = t + 128 * j;        // 0..255
            int r = u >> 2;             // row 0..63
            int q = u & 3;              // which uint2 of the bias/zero tail (cols 128..143)
            uint2 val = make_uint2(q == 0 ? one_bits : 0u, 0u);
            *(uint2*)(sm + r * LDA + 128 + q * 4) = val;
        }
    }

    #pragma unroll
    for (int m = 0; m < 4; m++) {
        if (m > 0) __syncthreads();     // all warps done with B[m-1] MMAs
        // load B[m]: 128 rows x 144 halfs = 2304 16B chunks (18 per row), strided to LDA
        {
            const uint4* gw = (const uint4*)(g_wt + (size_t)m * 128 * KAUG);
            uint32_t bb = sbase + SM_B * 2;
            #pragma unroll
            for (int j = 0; j < 18; j++) {
                int idx = t + 128 * j;      // 0..2303
                int n = idx / 18;
                int c = idx - n * 18;
                cp_async16(bb + (uint32_t)(n * LDA * 2 + c * 16), gw + idx);
            }
            asm volatile("cp.async.commit_group;");
            asm volatile("cp.async.wait_group 0;");
        }
        __syncthreads();   // B[m] (and A on m=0) visible to all

        const __half* B = sm + SM_B;

        wmma::fragment<wmma::accumulator, 16, 16, 16, float> acc[2][4];
        #pragma unroll
        for (int i = 0; i < 2; i++)
            #pragma unroll
            for (int j = 0; j < 4; j++)
                wmma::fill_fragment(acc[i][j], 0.0f);

        #pragma unroll
        for (int ks = 0; ks < 9; ks++) {
            wmma::fragment<wmma::matrix_a, 16, 16, 16, __half, wmma::row_major> af[2];
            #pragma unroll
            for (int i = 0; i < 2; i++)
                wmma::load_matrix_sync(af[i], sm + (wm * 32 + i * 16) * LDA + ks * 16, LDA);
            #pragma unroll
            for (int j = 0; j < 4; j++) {
                wmma::fragment<wmma::matrix_b, 16, 16, 16, __half, wmma::col_major> bf;
                wmma::load_matrix_sync(bf, B + (wn * 64 + j * 16) * LDA + ks * 16, LDA);
                wmma::mma_sync(acc[0][j], af[0], bf, acc[0][j]);
                wmma::mma_sync(acc[1][j], af[1], bf, acc[1][j]);
            }
        }

        // direct fp16 store to global (f32 acc -> f16 acc fragment, same element order)
        __half* dst;
        int ldo;
        if (m == 0)      { dst = g_qh  + (size_t)row0 * DIM; ldo = 128; }
        else if (m == 1) { dst = g_kvh + (size_t)row0 * 256; ldo = 256; }
        else if (m == 2) { dst = g_kvh + (size_t)row0 * 256 + 128; ldo = 256; }
        else             { dst = g_hh  + (size_t)row0 * DIM; ldo = 128; }

        #pragma unroll
        for (int i = 0; i < 2; i++)
            #pragma unroll
            for (int j = 0; j < 4; j++) {
                wmma::fragment<wmma::accumulator, 16, 16, 16, __half> hf;
                #pragma unroll
                for (int e = 0; e < hf.num_elements; e++)
                    hf.x[e] = __float2half(acc[i][j].x[e]);
                wmma::store_matrix_sync(
                    dst + (size_t)(wm * 32 + i * 16) * ldo + wn * 64 + j * 16,
                    hf, ldo, wmma::mem_row_major);
            }
    }
}

// ---------------- CSR build ----------------
__global__ void edge_hist(const int* __restrict__ eih, const int* __restrict__ eil)
{
    int e = blockIdx.x * 256 + threadIdx.x;
    if (e >= ET) return;
    int dst = (e < EHI) ? eih[EHI + e] : (eil[ELO + (e - EHI)] + NHI);
    atomicAdd(&g_dcnt[dst], 1);
}

__global__ void scan_local()
{
    __shared__ int sh[1024];
    const int t = threadIdx.x;
    const int i = blockIdx.x * 1024 + t;
    int v = g_dcnt[i];
    sh[t] = v;
    __syncthreads();
    #pragma unroll
    for (int off = 1; off < 1024; off <<= 1) {
        int u = (t >= off) ? sh[t - off] : 0;
        __syncthreads();
        sh[t] += u;
        __syncthreads();
    }
    g_rowptr[i] = sh[t] - v;            // local exclusive
    if (t == 1023) g_bsum[blockIdx.x] = sh[t];
}

__global__ void scan_bsum()
{
    __shared__ int sh[512];
    const int t = threadIdx.x;          // 512 threads
    int v = (t < NBLK) ? g_bsum[t] : 0;
    sh[t] = v;
    __syncthreads();
    #pragma unroll
    for (int off = 1; off < 512; off <<= 1) {
        int u = (t >= off) ? sh[t - off] : 0;
        __syncthreads();
        sh[t] += u;
        __syncthreads();
    }
    if (t < NBLK) g_bex[t] = sh[t] - v; // exclusive block base
    if (t == 511) g_rowptr[NT] = sh[511];
}

__global__ void scan_add()
{
    const int i = blockIdx.x * 1024 + threadIdx.x;
    int r = g_rowptr[i] + g_bex[blockIdx.x];
    g_rowptr[i] = r;
    g_cursor[i] = r;
}

__global__ void edge_scatter(const int* __restrict__ eih, const int* __restrict__ eil)
{
    int e = blockIdx.x * 256 + threadIdx.x;
    if (e >= ET) return;
    int src, dst;
    if (e < EHI) { src = eih[e];             dst = eih[EHI + e]; }
    else         { src = eil[e - EHI] + NHI; dst = eil[ELO + (e - EHI)] + NHI; }
    int pos = atomicAdd(&g_cursor[dst], 1);
    g_col[pos] = src;
}

// ---------------- K2: one-pass attention (plain exp; softmax is shift-invariant and
// scores are bounded ~|q||k|*SCALE < 25, far inside fp32 exp range) + fused LN/ReLU ----
// lane owns 4 contiguous columns [lane*4, lane*4+4); head = lane>>3.
__global__ void __launch_bounds__(256)
attn_ln(const float* __restrict__ lnw, const float* __restrict__ lnb)
{
    int node = blockIdx.x * 8 + threadIdx.y;
    int lane = threadIdx.x;
    int s = g_rowptr[node];
    int e1 = g_rowptr[node + 1];

    __half* hr = g_hh + (size_t)node * DIM;
    float4 val = hf8_to_f4(((uint2*)hr)[lane]);   // skip term

    if (s < e1) {
        float4 qv = hf8_to_f4(((const uint2*)(g_qh + (size_t)node * DIM))[lane]);

        float d = 0.f;
        float4 acc = make_float4(0.f, 0.f, 0.f, 0.f);

        // 1-deep software pipeline on the kv gather (512B contiguous per edge)
        const uint2* kvp = (const uint2*)(g_kvh + (size_t)g_col[s] * 256);
        uint2 kraw = kvp[lane];
        uint2 vraw = kvp[lane + 32];
        for (int i = s; i < e1; i++) {
            float4 kc = hf8_to_f4(kraw);
            float4 vc = hf8_to_f4(vraw);
            if (i + 1 < e1) {
                const uint2* np = (const uint2*)(g_kvh + (size_t)g_col[i + 1] * 256);
                kraw = np[lane];
                vraw = np[lane + 32];
            }
            float p = qv.x * kc.x + qv.y * kc.y + qv.z * kc.z + qv.w * kc.w;
            p += __shfl_xor_sync(0xffffffffu, p, 4);
            p += __shfl_xor_sync(0xffffffffu, p, 2);
            p += __shfl_xor_sync(0xffffffffu, p, 1);
            float w = __expf(p * SCALE);     // this lane's head weight
            d += w;
            acc.x += w * vc.x;
            acc.y += w * vc.y;
            acc.z += w * vc.z;
            acc.w += w * vc.w;
        }
        float inv = 1.0f / d;
        val.x += acc.x * inv;
        val.y += acc.y * inv;
        val.z += acc.z * inv;
        val.w += acc.w * inv;
    }

    // fused LayerNorm + ReLU (warp holds the full 128-dim row)
    float sum = warp_sum(val.x + val.y + val.z + val.w);
    float sq = warp_sum(val.x * val.x + val.y * val.y + val.z * val.z + val.w * val.w);
    float mean = sum * (1.0f / 128.0f);
    float var = sq * (1.0f / 128.0f) - mean * mean;
    float rstd = rsqrtf(var + 1e-5f);
    float4 w4 = ((const float4*)lnw)[lane];
    float4 b4 = ((const float4*)lnb)[lane];
    float4 o;
    o.x = fmaxf((val.x - mean) * rstd * w4.x + b4.x, 0.0f);
    o.y = fmaxf((val.y - mean) * rstd * w4.y + b4.y, 0.0f);
    o.z = fmaxf((val.z - mean) * rstd * w4.z + b4.z, 0.0f);
    o.w = fmaxf((val.w - mean) * rstd * w4.w + b4.w, 0.0f);
    ((uint2*)hr)[lane] = f4_to_hf8(o);
}

// ---------------- K3: segmented pool + high-node gating (one warp per high node) ----------------
__device__ __forceinline__ int lower_bound_batch(const int* __restrict__ batch, int key)
{
    int lo = 0, hi = NLO;
    while (lo < hi) {
        int mid = (lo + hi) >> 1;
        if (batch[mid] < key) lo = mid + 1; else hi = mid;
    }
    return lo;
}

__global__ void __launch_bounds__(256)
pool_final_high(const int* __restrict__ batch, const float* __restrict__ wlh,
                float* __restrict__ out)
{
    int g = blockIdx.x * 8 + threadIdx.y;
    int lane = threadIdx.x;
    int lb = lower_bound_batch(batch, g);
    int ub = lower_bound_batch(batch, g + 1);

    float4 s = make_float4(0.f, 0.f, 0.f, 0.f);
    for (int j = lb; j < ub; j++) {
        float4 lr = hf8_to_f4(((const uint2*)(g_hh + (size_t)(NHI + j) * DIM))[lane]);
        s.x += lr.x; s.y += lr.y; s.z += lr.z; s.w += lr.w;
    }
    float inv = 1.0f / fmaxf((float)(ub - lb), 1.0f);
    float4 pv = make_float4(s.x * inv, s.y * inv, s.z * inv, s.w * inv);

    float4 hv = hf8_to_f4(((const uint2*)(g_hh + (size_t)g * DIM))[lane]);
    float4 w0 = ((const float4*)wlh)[lane];
    float4 w1 = ((const float4*)(wlh + DIM))[lane];
    float dot = hv.x * w0.x + hv.y * w0.y + hv.z * w0.z + hv.w * w0.w
              + pv.x * w1.x + pv.y * w1.y + pv.z * w1.z + pv.w * w1.w;
    dot = warp_sum(dot);
    float sgm = 1.0f / (1.0f + __expf(-dot));
    float4 o;
    o.x = sgm * hv.x + (1.0f - sgm) * pv.x;
    o.y = sgm * hv.y + (1.0f - sgm) * pv.y;
    o.z = sgm * hv.z + (1.0f - sgm) * pv.z;
    o.w = sgm * hv.w + (1.0f - sgm) * pv.w;
    ((float4*)(out + (size_t)g * DIM))[lane] = o;
}

// ---------------- K4: low-node gating epilogue ----------------
__global__ void final_low(const float* __restrict__ whl, const int* __restrict__ batch,
                          float* __restrict__ out)
{
    int j = blockIdx.x * 8 + threadIdx.y;
    int lane = threadIdx.x;
    int g = batch[j];
    float4 hb = hf8_to_f4(((const uint2*)(g_hh + (size_t)g * DIM))[lane]);
    float4 lv = hf8_to_f4(((const uint2*)(g_hh + (size_t)(NHI + j) * DIM))[lane]);
    float4 w0 = ((const float4*)whl)[lane];
    float4 w1 = ((const float4*)(whl + DIM))[lane];
    float d = hb.x * w0.x + hb.y * w0.y + hb.z * w0.z + hb.w * w0.w
            + lv.x * w1.x + lv.y * w1.y + lv.z * w1.z + lv.w * w1.w;
    d = warp_sum(d);
    float a = 1.0f / (1.0f + __expf(-d));
    float4 o;
    o.x = a * lv.x + (1.0f - a) * hb.x;
    o.y = a * lv.y + (1.0f - a) * hb.y;
    o.z = a * lv.z + (1.0f - a) * hb.z;
    o.w = a * lv.w + (1.0f - a) * hb.w;
    ((float4*)(out + (size_t)j * DIM))[lane] = o;
}

// ---------------- launch ----------------
extern "C" void kernel_launch(void* const* d_in, const int* in_sizes, int n_in,
                              void* d_out, int out_size)
{
    const float* high_emb = (const float*)d_in[0];
    const float* low_emb  = (const float*)d_in[1];
    const float* Wq = (const float*)d_in[2];  const float* bq = (const float*)d_in[3];
    const float* Wk = (const float*)d_in[4];  const float* bk = (const float*)d_in[5];
    const float* Wv = (const float*)d_in[6];  const float* bv = (const float*)d_in[7];
    const float* Ws = (const float*)d_in[8];  const float* bs = (const float*)d_in[9];
    const float* lnw = (const float*)d_in[10];
    const float* lnb = (const float*)d_in[11];
    const float* wlh = (const float*)d_in[12];
    const float* whl = (const float*)d_in[13];
    const int* eih   = (const int*)d_in[14];
    const int* eil   = (const int*)d_in[15];
    const int* batch = (const int*)d_in[16];
    float* out = (float*)d_out;

    void* pcnt;
    cudaGetSymbolAddress(&pcnt, g_dcnt);

    cudaFuncSetAttribute(gemm_hmma, cudaFuncAttributeMaxDynamicSharedMemorySize, SM_BYTES);

    // second stream + fork/join events (graph-capture-legal pattern)
    cudaStream_t s2;
    cudaStreamCreateWithFlags(&s2, cudaStreamNonBlocking);
    cudaEvent_t evFork, evCsr, evAttn, evPool;
    cudaEventCreateWithFlags(&evFork, cudaEventDisableTiming);
    cudaEventCreateWithFlags(&evCsr,  cudaEventDisableTiming);
    cudaEventCreateWithFlags(&evAttn, cudaEventDisableTiming);
    cudaEventCreateWithFlags(&evPool, cudaEventDisableTiming);

    cudaMemsetAsync(pcnt, 0, NT * sizeof(int), 0);
    cudaEventRecord(evFork, 0);
    cudaStreamWaitEvent(s2, evFork, 0);

    // stream 0: prep + GEMM; s2: CSR chain concurrently
    prep_w<<<288, 256>>>(Wq, Wk, Wv, Ws, bq, bk, bv, bs);
    edge_hist<<<(ET + 255) / 256, 256, 0, s2>>>(eih, eil);
    gemm_hmma<<<NT / TILE_M, 128, SM_BYTES>>>(high_emb, low_emb);

    scan_local<<<NBLK, 1024, 0, s2>>>();
    scan_bsum<<<1, 512, 0, s2>>>();
    scan_add<<<NBLK, 1024, 0, s2>>>();
    edge_scatter<<<(ET + 255) / 256, 256, 0, s2>>>(eih, eil);
    cudaEventRecord(evCsr, s2);

    // join: attention needs both GEMM outputs and CSR
    cudaStreamWaitEvent(0, evCsr, 0);
    dim3 t32x8(32, 8);
    attn_ln<<<NT / 8, t32x8>>>(lnw, lnb);
    cudaEventRecord(evAttn, 0);

    // overlap the two epilogues
    cudaStreamWaitEvent(s2, evAttn, 0);
    pool_final_high<<<NHI / 8, t32x8, 0, s2>>>(batch, wlh, out);
    cudaEventRecord(evPool, s2);
    final_low<<<NLO / 8, t32x8>>>(whl, batch, out + (size_t)NHI * DIM);
    cudaStreamWaitEvent(0, evPool, 0);

    cudaEventDestroy(evFork);
    cudaEventDestroy(evCsr);
    cudaEventDestroy(evAttn);
    cudaEventDestroy(evPool);
    cudaStreamDestroy(s2);
}

// round 17
// speedup vs baseline: 1.1259x; 1.0278x over previous
#include <cuda_runtime.h>
#include <cuda_bf16.h>
#include <cuda_fp16.h>
#include <mma.h>
#include <math.h>
#include <cstdint>

using namespace nvcuda;

#define NHI 4096
#define NLO 262144
#define NT  (NHI + NLO)      /* 266240 = 260 * 1024 */
#define EHI 65536
#define ELO 524288
#define ET  (EHI + ELO)
#define DIM 128
#define KAUG 144             /* 128 + bias col + 15 zero pad (K extent for MMA) */
#define NHEAD 4
#define HDIM 32
#define SCALE 0.17677669529663687f   /* 1/sqrt(32) */
#define NBLK 260             /* scan blocks */

// ---------------- scratch (device globals; no allocation allowed) ----------------
__device__ __half g_qh[(size_t)NT * DIM];    // q (fp16)
__device__ __half g_kvh[(size_t)NT * 256];   // k at +0, v at +128 (fp16)
__device__ __half g_hh[(size_t)NT * DIM];    // skip -> +agg+LN+relu in place (fp16)
__device__ int g_dcnt[NT];
__device__ int g_rowptr[NT + 1];
__device__ int g_cursor[NT];
__device__ int g_col[ET];
__device__ int g_bsum[NBLK];
__device__ int g_bex[NBLK];
// W^T fp16 image with bias row: [matrix 0..3][n 0..127][k 0..143]
__device__ __align__(16) __half g_wt[4 * 128 * KAUG];

// ---------------- helpers ----------------
__device__ __forceinline__ float warp_sum(float v) {
    #pragma unroll
    for (int o = 16; o; o >>= 1) v += __shfl_xor_sync(0xffffffffu, v, o);
    return v;
}
__device__ __forceinline__ uint32_t smem_u32(const void* p) {
    uint32_t a;
    asm("{ .reg .u64 t; cvta.to.shared.u64 t, %1; cvt.u32.u64 %0, t; }"
        : "=r"(a) : "l"(p));
    return a;
}
__device__ __forceinline__ void cp_async16(uint32_t dst, const void* src) {
    asm volatile("cp.async.cg.shared.global [%0], [%1], 16;" :: "r"(dst), "l"(src));
}
__device__ __forceinline__ float4 hf8_to_f4(uint2 raw) {
    __half2 h0 = ((const __half2*)&raw)[0];
    __half2 h1 = ((const __half2*)&raw)[1];
    float2 f0 = __half22float2(h0);
    float2 f1 = __half22float2(h1);
    return make_float4(f0.x, f0.y, f1.x, f1.y);
}
__device__ __forceinline__ uint2 f4_to_hf8(float4 x) {
    __half2 p0 = __floats2half2_rn(x.x, x.y);
    __half2 p1 = __floats2half2_rn(x.z, x.w);
    return make_uint2(*(uint32_t*)&p0, *(uint32_t*)&p1);
}

// ---------------- K0: prep weights -> W^T fp16 with bias row at k=128 ----------------
__global__ void prep_w(const float* __restrict__ Wq, const float* __restrict__ Wk,
                       const float* __restrict__ Wv, const float* __restrict__ Ws,
                       const float* __restrict__ bq, const float* __restrict__ bk,
                       const float* __restrict__ bv, const float* __restrict__ bs)
{
    int idx = blockIdx.x * 256 + threadIdx.x;  // 0..73727
    if (idx >= 4 * 128 * KAUG) return;
    int m = idx / (128 * KAUG);
    int rem = idx - m * 128 * KAUG;
    int n = rem / KAUG;
    int k = rem - n * KAUG;
    const float* W = (m == 0) ? Wq : (m == 1) ? Wk : (m == 2) ? Wv : Ws;
    const float* B = (m == 0) ? bq : (m == 1) ? bk : (m == 2) ? bv : bs;
    float w = (k < 128) ? W[k * 128 + n] : (k == 128 ? B[n] : 0.0f);
    g_wt[idx] = __float2half(w);
}

// ---------------- K1: fused QKV+skip GEMM, fp16 HMMA, K=144, LDA=152, TILE_M=128 ----------------
// LDA = 152 halfs = 304B = 19 x 16B units (odd) -> ldmatrix conflict-free.
// SMEM (half elems): A[128*152], B[128*152]
#define TILE_M 128
#define LDA 152
#define A_ELEMS (TILE_M * LDA)          /* 19456 */
#define SM_B    A_ELEMS
#define SM_BYTES ((SM_B + 128 * LDA) * 2)   /* (19456+19456)*2 = 77824 */

__global__ void __launch_bounds__(256, 2)
gemm_hmma(const float* __restrict__ xh, const float* __restrict__ xl)
{
    extern __shared__ __half sm[];
    const uint32_t sbase = smem_u32(sm);
    const int t = threadIdx.x;       // 0..255
    const int wid = t >> 5;          // 0..7
    const int wm = wid & 3;          // warp row group: 32 rows (128-row tile)
    const int wn = wid >> 2;         // warp col group: 64 cols (128 cols)

    // ---- load + convert A tile (128 rows x 128 k) to fp16; cols 128..143 = {1,0,...} ----
    const int row0 = blockIdx.x * TILE_M;
    const float* X = (row0 < NHI) ? (xh + (size_t)row0 * DIM)
                                  : (xl + (size_t)(row0 - NHI) * DIM);
    #pragma unroll
    for (int j = 0; j < 16; j++) {
        int v = t + 256 * j;            // float4 index 0..4095
        int r = v >> 5;                 // row 0..127
        int k0 = (v & 31) * 4;          // k 0..124
        float4 x = ((const float4*)X)[v];
        *(uint2*)(sm + r * LDA + k0) = f4_to_hf8(x);
    }
    {
        __half2 one0 = __floats2half2_rn(1.0f, 0.0f);
        uint32_t one_bits = *(uint32_t*)&one0;
        #pragma unroll
        for (int j = 0; j < 2; j++) {
            int u = t + 256 * j;        // 0..511
            int r = u >> 2;             // row 0..127
            int q = u & 3;              // which uint2 of the bias/zero tail (cols 128..143)
            uint2 val = make_uint2(q == 0 ? one_bits : 0u, 0u);
            *(uint2*)(sm + r * LDA + 128 + q * 4) = val;
        }
    }

    #pragma unroll
    for (int m = 0; m < 4; m++) {
        if (m > 0) __syncthreads();     // all warps done with B[m-1] MMAs
        // load B[m]: 128 rows x 144 halfs = 2304 16B chunks (18 per row), strided to LDA
        {
            const uint4* gw = (const uint4*)(g_wt + (size_t)m * 128 * KAUG);
            uint32_t bb = sbase + SM_B * 2;
            #pragma unroll
            for (int j = 0; j < 9; j++) {
                int idx = t + 256 * j;      // 0..2303
                int n = idx / 18;
                int c = idx - n * 18;
                cp_async16(bb + (uint32_t)(n * LDA * 2 + c * 16), gw + idx);
            }
            asm volatile("cp.async.commit_group;");
            asm volatile("cp.async.wait_group 0;");
        }
        __syncthreads();   // B[m] (and A on m=0) visible to all

        const __half* B = sm + SM_B;

        wmma::fragment<wmma::accumulator, 16, 16, 16, float> acc[2][4];
        #pragma unroll
        for (int i = 0; i < 2; i++)
            #pragma unroll
            for (int j = 0; j < 4; j++)
                wmma::fill_fragment(acc[i][j], 0.0f);

        #pragma unroll
        for (int ks = 0; ks < 9; ks++) {
            wmma::fragment<wmma::matrix_a, 16, 16, 16, __half, wmma::row_major> af[2];
            #pragma unroll
            for (int i = 0; i < 2; i++)
                wmma::load_matrix_sync(af[i], sm + (wm * 32 + i * 16) * LDA + ks * 16, LDA);
            #pragma unroll
            for (int j = 0; j < 4; j++) {
                wmma::fragment<wmma::matrix_b, 16, 16, 16, __half, wmma::col_major> bf;
                wmma::load_matrix_sync(bf, B + (wn * 64 + j * 16) * LDA + ks * 16, LDA);
                wmma::mma_sync(acc[0][j], af[0], bf, acc[0][j]);
                wmma::mma_sync(acc[1][j], af[1], bf, acc[1][j]);
            }
        }

        // direct fp16 store to global (f32 acc -> f16 acc fragment, same element order)
        __half* dst;
        int ldo;
        if (m == 0)      { dst = g_qh  + (size_t)row0 * DIM; ldo = 128; }
        else if (m == 1) { dst = g_kvh + (size_t)row0 * 256; ldo = 256; }
        else if (m == 2) { dst = g_kvh + (size_t)row0 * 256 + 128; ldo = 256; }
        else             { dst = g_hh  + (size_t)row0 * DIM; ldo = 128; }

        #pragma unroll
        for (int i = 0; i < 2; i++)
            #pragma unroll
            for (int j = 0; j < 4; j++) {
                wmma::fragment<wmma::accumulator, 16, 16, 16, __half> hf;
                #pragma unroll
                for (int e = 0; e < hf.num_elements; e++)
                    hf.x[e] = __float2half(acc[i][j].x[e]);
                wmma::store_matrix_sync(
                    dst + (size_t)(wm * 32 + i * 16) * ldo + wn * 64 + j * 16,
                    hf, ldo, wmma::mem_row_major);
            }
    }
}

// ---------------- CSR build ----------------
__global__ void edge_hist(const int* __restrict__ eih, const int* __restrict__ eil)
{
    int e = blockIdx.x * 256 + threadIdx.x;
    if (e >= ET) return;
    int dst = (e < EHI) ? eih[EHI + e] : (eil[ELO + (e - EHI)] + NHI);
    atomicAdd(&g_dcnt[dst], 1);
}

__global__ void scan_local()
{
    __shared__ int sh[1024];
    const int t = threadIdx.x;
    const int i = blockIdx.x * 1024 + t;
    int v = g_dcnt[i];
    sh[t] = v;
    __syncthreads();
    #pragma unroll
    for (int off = 1; off < 1024; off <<= 1) {
        int u = (t >= off) ? sh[t - off] : 0;
        __syncthreads();
        sh[t] += u;
        __syncthreads();
    }
    g_rowptr[i] = sh[t] - v;            // local exclusive
    if (t == 1023) g_bsum[blockIdx.x] = sh[t];
}

__global__ void scan_bsum()
{
    __shared__ int sh[512];
    const int t = threadIdx.x;          // 512 threads
    int v = (t < NBLK) ? g_bsum[t] : 0;
    sh[t] = v;
    __syncthreads();
    #pragma unroll
    for (int off = 1; off < 512; off <<= 1) {
        int u = (t >= off) ? sh[t - off] : 0;
        __syncthreads();
        sh[t] += u;
        __syncthreads();
    }
    if (t < NBLK) g_bex[t] = sh[t] - v; // exclusive block base
    if (t == 511) g_rowptr[NT] = sh[511];
}

__global__ void scan_add()
{
    const int i = blockIdx.x * 1024 + threadIdx.x;
    int r = g_rowptr[i] + g_bex[blockIdx.x];
    g_rowptr[i] = r;
    g_cursor[i] = r;
}

__global__ void edge_scatter(const int* __restrict__ eih, const int* __restrict__ eil)
{
    int e = blockIdx.x * 256 + threadIdx.x;
    if (e >= ET) return;
    int src, dst;
    if (e < EHI) { src = eih[e];             dst = eih[EHI + e]; }
    else         { src = eil[e - EHI] + NHI; dst = eil[ELO + (e - EHI)] + NHI; }
    int pos = atomicAdd(&g_cursor[dst], 1);
    g_col[pos] = src;
}

// ---------------- shared attention body: returns LN'd row for `node` ----------------
__device__ __forceinline__ float4 attn_ln_body(int node, int lane,
                                               const float* __restrict__ lnw,
                                               const float* __restrict__ lnb)
{
    int s = g_rowptr[node];
    int e1 = g_rowptr[node + 1];

    __half* hr = g_hh + (size_t)node * DIM;
    float4 val = hf8_to_f4(((uint2*)hr)[lane]);   // skip term

    if (s < e1) {
        float4 qv = hf8_to_f4(((const uint2*)(g_qh + (size_t)node * DIM))[lane]);

        float d = 0.f;
        float4 acc = make_float4(0.f, 0.f, 0.f, 0.f);

        // 1-deep software pipeline on the kv gather (512B contiguous per edge)
        const uint2* kvp = (const uint2*)(g_kvh + (size_t)g_col[s] * 256);
        uint2 kraw = kvp[lane];
        uint2 vraw = kvp[lane + 32];
        for (int i = s; i < e1; i++) {
            float4 kc = hf8_to_f4(kraw);
            float4 vc = hf8_to_f4(vraw);
            if (i + 1 < e1) {
                const uint2* np = (const uint2*)(g_kvh + (size_t)g_col[i + 1] * 256);
                kraw = np[lane];
                vraw = np[lane + 32];
            }
            float p = qv.x * kc.x + qv.y * kc.y + qv.z * kc.z + qv.w * kc.w;
            p += __shfl_xor_sync(0xffffffffu, p, 4);
            p += __shfl_xor_sync(0xffffffffu, p, 2);
            p += __shfl_xor_sync(0xffffffffu, p, 1);
            float w = __expf(p * SCALE);     // this lane's head weight (plain exp: scores bounded)
            d += w;
            acc.x += w * vc.x;
            acc.y += w * vc.y;
            acc.z += w * vc.z;
            acc.w += w * vc.w;
        }
        float inv = 1.0f / d;
        val.x += acc.x * inv;
        val.y += acc.y * inv;
        val.z += acc.z * inv;
        val.w += acc.w * inv;
    }

    // fused LayerNorm + ReLU (warp holds the full 128-dim row)
    float sum = warp_sum(val.x + val.y + val.z + val.w);
    float sq = warp_sum(val.x * val.x + val.y * val.y + val.z * val.z + val.w * val.w);
    float mean = sum * (1.0f / 128.0f);
    float var = sq * (1.0f / 128.0f) - mean * mean;
    float rstd = rsqrtf(var + 1e-5f);
    float4 w4 = ((const float4*)lnw)[lane];
    float4 b4 = ((const float4*)lnb)[lane];
    float4 o;
    o.x = fmaxf((val.x - mean) * rstd * w4.x + b4.x, 0.0f);
    o.y = fmaxf((val.y - mean) * rstd * w4.y + b4.y, 0.0f);
    o.z = fmaxf((val.z - mean) * rstd * w4.z + b4.z, 0.0f);
    o.w = fmaxf((val.w - mean) * rstd * w4.w + b4.w, 0.0f);
    ((uint2*)hr)[lane] = f4_to_hf8(o);
    return o;
}

// ---------------- K2a: attention + LN for HIGH nodes ----------------
__global__ void __launch_bounds__(256)
attn_ln_high(const float* __restrict__ lnw, const float* __restrict__ lnb)
{
    int node = blockIdx.x * 8 + threadIdx.y;   // 0..NHI-1
    attn_ln_body(node, threadIdx.x, lnw, lnb);
}

// ---------------- K2b: attention + LN for LOW nodes, fused with final_low gating ----------------
__global__ void __launch_bounds__(256)
attn_ln_low(const float* __restrict__ lnw, const float* __restrict__ lnb,
            const float* __restrict__ whl, const int* __restrict__ batch,
            float* __restrict__ out)
{
    int j = blockIdx.x * 8 + threadIdx.y;      // low index 0..NLO-1
    int lane = threadIdx.x;
    float4 lv = attn_ln_body(NHI + j, lane, lnw, lnb);

    // final_low gating (high rows in g_hh are complete: prior launch)
    int g = batch[j];
    float4 hb = hf8_to_f4(((const uint2*)(g_hh + (size_t)g * DIM))[lane]);
    float4 w0 = ((const float4*)whl)[lane];
    float4 w1 = ((const float4*)(whl + DIM))[lane];
    float d = hb.x * w0.x + hb.y * w0.y + hb.z * w0.z + hb.w * w0.w
            + lv.x * w1.x + lv.y * w1.y + lv.z * w1.z + lv.w * w1.w;
    d = warp_sum(d);
    float a = 1.0f / (1.0f + __expf(-d));
    float4 o;
    o.x = a * lv.x + (1.0f - a) * hb.x;
    o.y = a * lv.y + (1.0f - a) * hb.y;
    o.z = a * lv.z + (1.0f - a) * hb.z;
    o.w = a * lv.w + (1.0f - a) * hb.w;
    ((float4*)(out + (size_t)j * DIM))[lane] = o;
}

// ---------------- K3: segmented pool + high-node gating (one warp per high node) ----------------
__device__ __forceinline__ int lower_bound_batch(const int* __restrict__ batch, int key)
{
    int lo = 0, hi = NLO;
    while (lo < hi) {
        int mid = (lo + hi) >> 1;
        if (batch[mid] < key) lo = mid + 1; else hi = mid;
    }
    return lo;
}

__global__ void __launch_bounds__(256)
pool_final_high(const int* __restrict__ batch, const float* __restrict__ wlh,
                float* __restrict__ out)
{
    int g = blockIdx.x * 8 + threadIdx.y;
    int lane = threadIdx.x;
    int lb = lower_bound_batch(batch, g);
    int ub = lower_bound_batch(batch, g + 1);

    float4 s = make_float4(0.f, 0.f, 0.f, 0.f);
    for (int j = lb; j < ub; j++) {
        float4 lr = hf8_to_f4(((const uint2*)(g_hh + (size_t)(NHI + j) * DIM))[lane]);
        s.x += lr.x; s.y += lr.y; s.z += lr.z; s.w += lr.w;
    }
    float inv = 1.0f / fmaxf((float)(ub - lb), 1.0f);
    float4 pv = make_float4(s.x * inv, s.y * inv, s.z * inv, s.w * inv);

    float4 hv = hf8_to_f4(((const uint2*)(g_hh + (size_t)g * DIM))[lane]);
    float4 w0 = ((const float4*)wlh)[lane];
    float4 w1 = ((const float4*)(wlh + DIM))[lane];
    float dot = hv.x * w0.x + hv.y * w0.y + hv.z * w0.z + hv.w * w0.w
              + pv.x * w1.x + pv.y * w1.y + pv.z * w1.z + pv.w * w1.w;
    dot = warp_sum(dot);
    float sgm = 1.0f / (1.0f + __expf(-dot));
    float4 o;
    o.x = sgm * hv.x + (1.0f - sgm) * pv.x;
    o.y = sgm * hv.y + (1.0f - sgm) * pv.y;
    o.z = sgm * hv.z + (1.0f - sgm) * pv.z;
    o.w = sgm * hv.w + (1.0f - sgm) * pv.w;
    ((float4*)(out + (size_t)g * DIM))[lane] = o;
}

// ---------------- launch ----------------
extern "C" void kernel_launch(void* const* d_in, const int* in_sizes, int n_in,
                              void* d_out, int out_size)
{
    const float* high_emb = (const float*)d_in[0];
    const float* low_emb  = (const float*)d_in[1];
    const float* Wq = (const float*)d_in[2];  const float* bq = (const float*)d_in[3];
    const float* Wk = (const float*)d_in[4];  const float* bk = (const float*)d_in[5];
    const float* Wv = (const float*)d_in[6];  const float* bv = (const float*)d_in[7];
    const float* Ws = (const float*)d_in[8];  const float* bs = (const float*)d_in[9];
    const float* lnw = (const float*)d_in[10];
    const float* lnb = (const float*)d_in[11];
    const float* wlh = (const float*)d_in[12];
    const float* whl = (const float*)d_in[13];
    const int* eih   = (const int*)d_in[14];
    const int* eil   = (const int*)d_in[15];
    const int* batch = (const int*)d_in[16];
    float* out = (float*)d_out;

    void* pcnt;
    cudaGetSymbolAddress(&pcnt, g_dcnt);

    cudaFuncSetAttribute(gemm_hmma, cudaFuncAttributeMaxDynamicSharedMemorySize, SM_BYTES);

    // second stream + fork/join events (graph-capture-legal pattern)
    cudaStream_t s2;
    cudaStreamCreateWithFlags(&s2, cudaStreamNonBlocking);
    cudaEvent_t evFork, evCsr, evAttn, evPool;
    cudaEventCreateWithFlags(&evFork, cudaEventDisableTiming);
    cudaEventCreateWithFlags(&evCsr,  cudaEventDisableTiming);
    cudaEventCreateWithFlags(&evAttn, cudaEventDisableTiming);
    cudaEventCreateWithFlags(&evPool, cudaEventDisableTiming);

    cudaMemsetAsync(pcnt, 0, NT * sizeof(int), 0);
    cudaEventRecord(evFork, 0);
    cudaStreamWaitEvent(s2, evFork, 0);

    // stream 0: prep + GEMM; s2: CSR chain concurrently
    prep_w<<<288, 256>>>(Wq, Wk, Wv, Ws, bq, bk, bv, bs);
    edge_hist<<<(ET + 255) / 256, 256, 0, s2>>>(eih, eil);
    gemm_hmma<<<NT / TILE_M, 256, SM_BYTES>>>(high_emb, low_emb);

    scan_local<<<NBLK, 1024, 0, s2>>>();
    scan_bsum<<<1, 512, 0, s2>>>();
    scan_add<<<NBLK, 1024, 0, s2>>>();
    edge_scatter<<<(ET + 255) / 256, 256, 0, s2>>>(eih, eil);
    cudaEventRecord(evCsr, s2);

    // join: attention needs both GEMM outputs and CSR
    cudaStreamWaitEvent(0, evCsr, 0);
    dim3 t32x8(32, 8);
    attn_ln_high<<<NHI / 8, t32x8>>>(lnw, lnb);
    attn_ln_low<<<NLO / 8, t32x8>>>(lnw, lnb, whl, batch, out + (size_t)NHI * DIM);
    cudaEventRecord(evAttn, 0);

    // pool+final_high on s2 (needs all low rows in g_hh)
    cudaStreamWaitEvent(s2, evAttn, 0);
    pool_final_high<<<NHI / 8, t32x8, 0, s2>>>(batch, wlh, out);
    cudaEventRecord(evPool, s2);
    cudaStreamWaitEvent(0, evPool, 0);

    cudaEventDestroy(evFork);
    cudaEventDestroy(evCsr);
    cudaEventDestroy(evAttn);
    cudaEventDestroy(evPool);
    cudaStreamDestroy(s2);
}